// round 4
// baseline (speedup 1.0000x reference)
#include <cuda_runtime.h>

// Input:  x (2,8,256,256) fp32, F (3,3) fp32
// Output: (2,8,256,256) fp32 epipolar line-sum.
//
// Strategy: repack x into g_t[h][w][p] (p = b*8+c, 16 channels contiguous = 64B)
// so the shared gather index (yi,x) serves all 16 planes with 4x LDG.128.

#define HSZ 256
#define WSZ 256
#define NPLANE 16

__device__ float g_t[HSZ * WSZ * NPLANE];   // 4 MB scratch (static, allocation-free)

__global__ void __launch_bounds__(256) transpose_k(const float* __restrict__ in) {
    int idx = blockIdx.x * 256 + threadIdx.x;     // idx = h*256 + w
    float buf[16];
#pragma unroll
    for (int p = 0; p < 16; ++p)
        buf[p] = __ldg(in + p * 65536 + idx);     // coalesced across warp per plane
    float4* dst = reinterpret_cast<float4*>(g_t + idx * 16);
#pragma unroll
    for (int q = 0; q < 4; ++q)
        dst[q] = make_float4(buf[4*q], buf[4*q+1], buf[4*q+2], buf[4*q+3]);
}

__global__ void __launch_bounds__(256) epi_k(const float* __restrict__ Fm,
                                             float* __restrict__ out) {
    const int pg = threadIdx.x & 3;               // channel group (4 planes)
    const int w  = (blockIdx.y << 6) + (threadIdx.x >> 2);
    const int h  = blockIdx.x;
    const float u = (float)w, v = (float)h;

    // l_i = sum_j F[j,i] * p_j — GEMM-style fma k-chain (cuBLAS/Eigen order):
    //   acc = fma(F[2,i], 1, fma(F[1,i], v, fma(F[0,i], u, 0)))
    const float F0 = __ldg(Fm+0), F1 = __ldg(Fm+1), F2 = __ldg(Fm+2);
    const float F3 = __ldg(Fm+3), F4 = __ldg(Fm+4), F5 = __ldg(Fm+5);
    const float F6 = __ldg(Fm+6), F7 = __ldg(Fm+7), F8 = __ldg(Fm+8);
    float A = __fadd_rn(__fmaf_rn(F3, v, __fmul_rn(F0, u)), F6);
    float B = __fadd_rn(__fmaf_rn(F4, v, __fmul_rn(F1, u)), F7);
    float C = __fadd_rn(__fmaf_rn(F5, v, __fmul_rn(F2, u)), F8);

    const bool col = (fabsf(B) >= fabsf(A));      // use_col = |b| >= |a|
    float P, Q;
    if (col) { P = A; Q = (fabsf(B) < 1e-8f) ? 1e-8f : B; }
    else     { P = B; Q = (fabsf(A) < 1e-8f) ? 1e-8f : A; }
    const float rq = __frcp_rn(Q);                // correctly-rounded reciprocal

    float4 acc = make_float4(0.f, 0.f, 0.f, 0.f);
    const float4* __restrict__ tptr = reinterpret_cast<const float4*>(g_t);

    float tf = 0.f;
#pragma unroll 4
    for (int t = 0; t < 256; ++t, tf += 1.f) {
        // reference scan body with XLA fp-contraction: n = fma(P, t, C),
        // y = (-n) / Q with IEEE divide.  (-fma(a,x,c) == fma(-a,x,-c) bitwise.)
        float n   = __fmaf_rn(P, tf, C);
        float num = -n;
        float yf  = __fmul_rn(num, rq);           // fast path (<= ~2 ulp off)
        int   ci  = __float2int_rn(yf);           // round half-to-even
        float d   = yf - (float)ci;
        if (0.5f - fabsf(d) < 5e-4f) {            // near a .5 boundary: be exact
            ci = __float2int_rn(__fdiv_rn(num, Q));
        }
        if ((unsigned)ci < 256u) {
            int sidx = col ? (ci * 256 + t) : (t * 256 + ci);
            float4 s = __ldg(tptr + sidx * 4 + pg);
            acc.x += s.x; acc.y += s.y; acc.z += s.z; acc.w += s.w;
        }
    }

    const int base = h * 256 + w;
    float* av = &acc.x;
#pragma unroll
    for (int j = 0; j < 4; ++j)
        out[(pg * 4 + j) * 65536 + base] = av[j];
}

extern "C" void kernel_launch(void* const* d_in, const int* in_sizes, int n_in,
                              void* d_out, int out_size) {
    const float* img = (const float*)d_in[0];
    const float* F   = (const float*)d_in[1];
    if (n_in >= 2 && in_sizes[0] == 9) {          // defensive: input order swap
        img = (const float*)d_in[1];
        F   = (const float*)d_in[0];
    }
    float* out = (float*)d_out;

    transpose_k<<<256, 256>>>(img);
    dim3 grid(256, 4);
    epi_k<<<grid, 256>>>(F, out);
}

// round 5
// speedup vs baseline: 1.1830x; 1.1830x over previous
#include <cuda_runtime.h>

// Input:  x (2,8,256,256) fp32, F (3,3) fp32
// Output: (2,8,256,256) fp32 epipolar line-sum.
//
// g_t[h][w][p]: 16 channels contiguous (64 B) per pixel.
// epi_k lane layout: lane = pg(0..3) + 4*parity(t&1) + 8*pix(0..3)
//   -> 8 lanes cover one pixel's (t, t+1) chunk pair = one 128-B line
//      whenever ci(t)==ci(t+1)  (true ~78% of steps for this F: slope<=0.22).

#define HSZ 256
#define WSZ 256
#define NPLANE 16

__device__ float g_t[HSZ * WSZ * NPLANE];   // 4 MB scratch (static, allocation-free)

__global__ void __launch_bounds__(256) transpose_k(const float* __restrict__ in) {
    int idx = blockIdx.x * 256 + threadIdx.x;     // idx = h*256 + w
    float buf[16];
#pragma unroll
    for (int p = 0; p < 16; ++p)
        buf[p] = __ldg(in + p * 65536 + idx);
    float4* dst = reinterpret_cast<float4*>(g_t + idx * 16);
#pragma unroll
    for (int q = 0; q < 4; ++q)
        dst[q] = make_float4(buf[4*q], buf[4*q+1], buf[4*q+2], buf[4*q+3]);
}

__global__ void __launch_bounds__(256) epi_k(const float* __restrict__ Fm,
                                             float* __restrict__ out) {
    const int lane   = threadIdx.x & 31;
    const int warp   = threadIdx.x >> 5;          // 0..7
    const int pg     = lane & 3;                  // float4 within pixel chunk
    const int parity = (lane >> 2) & 1;           // t parity handled by this lane
    const int pix    = lane >> 3;                 // 0..3 pixel within warp
    const int w = (blockIdx.y << 5) + (warp << 2) + pix;   // 32 w per block
    const int h = blockIdx.x;
    const float u = (float)w, v = (float)h;

    // Coefficients — EXACT arithmetic from the passing R4 kernel. Do not touch.
    const float F0 = __ldg(Fm+0), F1 = __ldg(Fm+1), F2 = __ldg(Fm+2);
    const float F3 = __ldg(Fm+3), F4 = __ldg(Fm+4), F5 = __ldg(Fm+5);
    const float F6 = __ldg(Fm+6), F7 = __ldg(Fm+7), F8 = __ldg(Fm+8);
    float A = __fadd_rn(__fmaf_rn(F3, v, __fmul_rn(F0, u)), F6);
    float B = __fadd_rn(__fmaf_rn(F4, v, __fmul_rn(F1, u)), F7);
    float C = __fadd_rn(__fmaf_rn(F5, v, __fmul_rn(F2, u)), F8);

    const bool col = (fabsf(B) >= fabsf(A));      // use_col = |b| >= |a|
    float P, Q;
    if (col) { P = A; Q = (fabsf(B) < 1e-8f) ? 1e-8f : B; }
    else     { P = B; Q = (fabsf(A) < 1e-8f) ? 1e-8f : A; }
    const float rq  = __frcp_rn(Q);
    const float nrq = -rq;                        // n*(-rq) == (-n)*rq bitwise
    const int m1 = col ? 256 : 1;                 // sidx = ci*m1 + t*m2
    const int m2 = col ? 1 : 256;

    float4 acc = make_float4(0.f, 0.f, 0.f, 0.f);
    const float4* __restrict__ tptr = reinterpret_cast<const float4*>(g_t);

    float tf = (float)parity;
    int   ti = parity;
#pragma unroll 4
    for (int k = 0; k < 128; ++k) {
        // EXACT R4 scan-body semantics: n = fma(P,t,C); y = (-n)/Q IEEE.
        float n  = __fmaf_rn(P, tf, C);
        float yf = __fmul_rn(n, nrq);             // fast path (<= ~2 ulp off)
        int   ci = __float2int_rn(yf);            // round half-to-even
        float d  = yf - (float)ci;
        if (0.5f - fabsf(d) < 5e-4f) {            // near a .5 boundary: be exact
            ci = __float2int_rn(__fdiv_rn(-n, Q));
        }
        if ((unsigned)ci < 256u) {
            int sidx = ci * m1 + ti * m2;
            float4 s = __ldg(tptr + sidx * 4 + pg);
            acc.x += s.x; acc.y += s.y; acc.z += s.z; acc.w += s.w;
        }
        tf += 2.0f; ti += 2;
    }

    // Combine t-parities (lane ^ 4 is the partner with same pg, pix).
    acc.x += __shfl_xor_sync(0xffffffffu, acc.x, 4);
    acc.y += __shfl_xor_sync(0xffffffffu, acc.y, 4);
    acc.z += __shfl_xor_sync(0xffffffffu, acc.z, 4);
    acc.w += __shfl_xor_sync(0xffffffffu, acc.w, 4);

    // Both parity lanes hold the full 4-plane sum; split the stores.
    const int base = h * 256 + w;
    const int p0 = pg * 4 + parity * 2;
    float v0 = parity ? acc.z : acc.x;
    float v1 = parity ? acc.w : acc.y;
    out[(p0    ) * 65536 + base] = v0;
    out[(p0 + 1) * 65536 + base] = v1;
}

extern "C" void kernel_launch(void* const* d_in, const int* in_sizes, int n_in,
                              void* d_out, int out_size) {
    const float* img = (const float*)d_in[0];
    const float* F   = (const float*)d_in[1];
    if (n_in >= 2 && in_sizes[0] == 9) {          // defensive: input order swap
        img = (const float*)d_in[1];
        F   = (const float*)d_in[0];
    }
    float* out = (float*)d_out;

    transpose_k<<<256, 256>>>(img);
    dim3 grid(256, 8);                            // h x (w/32)
    epi_k<<<grid, 256>>>(F, out);
}

// round 7
// speedup vs baseline: 1.2350x; 1.0440x over previous
#include <cuda_runtime.h>
#include <cstdint>

// Input:  x (2,8,256,256) fp32, F (3,3) fp32
// Output: (2,8,256,256) fp32 epipolar line-sum.
//
// 3-kernel plan:
//  1) transpose_k: repack x -> g_t[h][w][p] (16 channels contiguous, 64 B/pixel)
//  2) index_k:     ci(h,w,t) once per (pixel,t), EXACT R5 arithmetic, int16
//  3) gather_k:    slim gather: extract idx, LDG.128, packed f32x2 accumulate

#define HSZ 256
#define WSZ 256
#define NPLANE 16

__device__ float   g_t[HSZ * WSZ * NPLANE];          // 4 MB repacked image
__device__ int16_t g_idx[HSZ * WSZ * 256];           // 33.5 MB: ci per (pixel,t), -1 invalid

#define ADD_F32X2(out, a, b) \
    asm("add.rn.f32x2 %0, %1, %2;" : "=l"(out) : "l"(a), "l"(b))
#define UNPACK_F32X2(lo, hi, in) \
    asm("mov.b64 {%0, %1}, %2;" : "=r"(lo), "=r"(hi) : "l"(in))

__global__ void __launch_bounds__(256) transpose_k(const float* __restrict__ in) {
    int idx = blockIdx.x * 256 + threadIdx.x;        // idx = h*256 + w
    float buf[16];
#pragma unroll
    for (int p = 0; p < 16; ++p)
        buf[p] = __ldg(in + p * 65536 + idx);
    float4* dst = reinterpret_cast<float4*>(g_t + idx * 16);
#pragma unroll
    for (int q = 0; q < 4; ++q)
        dst[q] = make_float4(buf[4*q], buf[4*q+1], buf[4*q+2], buf[4*q+3]);
}

// One thread = one (pixel, 8-t batch). EXACT R4/R5 arithmetic — do not touch.
__global__ void __launch_bounds__(256) index_k(const float* __restrict__ Fm) {
    const int tid = threadIdx.x;
    const int bt  = tid & 31;                        // t-batch (8 t's)
    const int w   = (blockIdx.y << 3) + (tid >> 5);
    const int h   = blockIdx.x;
    const float u = (float)w, v = (float)h;

    const float F0 = __ldg(Fm+0), F1 = __ldg(Fm+1), F2 = __ldg(Fm+2);
    const float F3 = __ldg(Fm+3), F4 = __ldg(Fm+4), F5 = __ldg(Fm+5);
    const float F6 = __ldg(Fm+6), F7 = __ldg(Fm+7), F8 = __ldg(Fm+8);
    float A = __fadd_rn(__fmaf_rn(F3, v, __fmul_rn(F0, u)), F6);
    float B = __fadd_rn(__fmaf_rn(F4, v, __fmul_rn(F1, u)), F7);
    float C = __fadd_rn(__fmaf_rn(F5, v, __fmul_rn(F2, u)), F8);

    const bool col = (fabsf(B) >= fabsf(A));
    float P, Q;
    if (col) { P = A; Q = (fabsf(B) < 1e-8f) ? 1e-8f : B; }
    else     { P = B; Q = (fabsf(A) < 1e-8f) ? 1e-8f : A; }
    const float rq  = __frcp_rn(Q);
    const float nrq = -rq;

    int16_t res[8];
    float tf = (float)(bt * 8);
#pragma unroll
    for (int j = 0; j < 8; ++j, tf += 1.0f) {
        float n  = __fmaf_rn(P, tf, C);
        float yf = __fmul_rn(n, nrq);                // fast path (<= ~2 ulp off)
        int   ci = __float2int_rn(yf);               // round half-to-even
        float d  = yf - (float)ci;
        if (0.5f - fabsf(d) < 5e-4f) {               // near .5 boundary: be exact
            ci = __float2int_rn(__fdiv_rn(-n, Q));
        }
        res[j] = ((unsigned)ci < 256u) ? (int16_t)ci : (int16_t)(-1);
    }
    reinterpret_cast<uint4*>(g_idx)[(h * 256 + w) * 32 + bt] =
        *reinterpret_cast<const uint4*>(res);
}

// Lane layout (as R5): lane = pg(0..3) + 4*parity + 8*pix(0..3); warp = 4 pixels.
__global__ void __launch_bounds__(256) gather_k(const float* __restrict__ Fm,
                                                float* __restrict__ out) {
    const int lane   = threadIdx.x & 31;
    const int warp   = threadIdx.x >> 5;
    const int pg     = lane & 3;
    const int parity = (lane >> 2) & 1;
    const int pix    = lane >> 3;
    const int w = (blockIdx.y << 5) + (warp << 2) + pix;
    const int h = blockIdx.x;
    const float u = (float)w, v = (float)h;

    // Only need the col/row mode bit here (exact same computation as index_k).
    const float F0 = __ldg(Fm+0), F1 = __ldg(Fm+1);
    const float F3 = __ldg(Fm+3), F4 = __ldg(Fm+4);
    const float F6 = __ldg(Fm+6), F7 = __ldg(Fm+7);
    float A = __fadd_rn(__fmaf_rn(F3, v, __fmul_rn(F0, u)), F6);
    float B = __fadd_rn(__fmaf_rn(F4, v, __fmul_rn(F1, u)), F7);
    const bool col = (fabsf(B) >= fabsf(A));
    const int m1 = col ? 256 : 1;                    // sidx = ci*m1 + t*m2
    const int m2 = col ? 1 : 256;
    const int m2x2 = m2 * 2;

    const uint4* __restrict__ ip =
        reinterpret_cast<const uint4*>(g_idx) + (h * 256 + w) * 32;
    const ulonglong2* __restrict__ tp =
        reinterpret_cast<const ulonglong2*>(g_t);

    unsigned long long acc0 = 0ull, acc1 = 0ull;     // packed {+0,+0} f32x2
    int tim2 = parity * m2;                          // t*m2 running term

#pragma unroll 4
    for (int b = 0; b < 32; ++b) {
        uint4 iv = __ldg(ip + b);                    // 8 int16 indices (broadcast)
        unsigned wv[4] = {iv.x, iv.y, iv.z, iv.w};
#pragma unroll
        for (int j = 0; j < 4; ++j) {
            // word j holds ci(t=b*8+2j) in lo half, ci(t=b*8+2j+1) in hi half
            int ci = parity ? ((int)wv[j] >> 16)
                            : (((int)(wv[j] << 16)) >> 16);
            if (ci >= 0) {
                int sidx = ci * m1 + tim2;
                ulonglong2 s = __ldg(tp + (sidx * 4 + pg));
                ADD_F32X2(acc0, acc0, s.x);
                ADD_F32X2(acc1, acc1, s.y);
            }
            tim2 += m2x2;
        }
    }

    unsigned rx, ry, rz, rw;
    UNPACK_F32X2(rx, ry, acc0);
    UNPACK_F32X2(rz, rw, acc1);
    float ax = __uint_as_float(rx), ay = __uint_as_float(ry);
    float az = __uint_as_float(rz), aw = __uint_as_float(rw);

    // Combine t-parities (lane ^ 4 = partner with same pg, pix).
    ax += __shfl_xor_sync(0xffffffffu, ax, 4);
    ay += __shfl_xor_sync(0xffffffffu, ay, 4);
    az += __shfl_xor_sync(0xffffffffu, az, 4);
    aw += __shfl_xor_sync(0xffffffffu, aw, 4);

    const int base = h * 256 + w;
    const int p0 = pg * 4 + parity * 2;
    float v0 = parity ? az : ax;
    float v1 = parity ? aw : ay;
    out[(p0    ) * 65536 + base] = v0;
    out[(p0 + 1) * 65536 + base] = v1;
}

extern "C" void kernel_launch(void* const* d_in, const int* in_sizes, int n_in,
                              void* d_out, int out_size) {
    const float* img = (const float*)d_in[0];
    const float* F   = (const float*)d_in[1];
    if (n_in >= 2 && in_sizes[0] == 9) {             // defensive: input order swap
        img = (const float*)d_in[1];
        F   = (const float*)d_in[0];
    }
    float* out = (float*)d_out;

    transpose_k<<<256, 256>>>(img);
    dim3 gidx(256, 32);
    index_k<<<gidx, 256>>>(F);
    dim3 ggat(256, 8);
    gather_k<<<ggat, 256>>>(F, out);
}

// round 8
// speedup vs baseline: 1.4092x; 1.1410x over previous
#include <cuda_runtime.h>
#include <cstdint>

// Input:  x (2,8,256,256) fp32, F (3,3) fp32
// Output: (2,8,256,256) fp32 epipolar line-sum.
//
// Pipeline:
//  1) transpose_k : x -> g_t[h][w][p], 16 channels contiguous (64 B/pixel)
//  2) index_k     : exact per-(pixel,t) sample index ci (EXACT R7 arithmetic)
//  3) rle_k       : warp/pixel run-length-encode ci(t) -> packed (ci,t0,t1)
//  4) prefix_col_k/prefix_row_k : exclusive prefix tables P[line][t][p]
//  5) gather_k    : per run: acc += P[ci][t1] - P[ci][t0]   (2 loads/run)

#define FULLM 0xffffffffu

__device__ float4   g_t4 [256 * 256 * 4];        // 4 MB   repacked image (float4 = 4 planes)
__device__ int16_t  g_idx[256 * 256 * 256];      // 33.5MB per-t index, -1 invalid
__device__ unsigned g_run[256 * 256 * 264];      // 69 MB  packed runs: ci|t0<<9|t1<<18
__device__ int      g_nrun[256 * 256];
__device__ float4   g_pc [256 * 257 * 4];        // 4.2MB  col prefix: line=h, t=w
__device__ float4   g_pr [256 * 257 * 4];        // 4.2MB  row prefix: line=w, t=h

__global__ void __launch_bounds__(256) transpose_k(const float* __restrict__ in) {
    int gid = blockIdx.x * 256 + threadIdx.x;    // 262144 = 65536 px * 4 groups
    int px = gid >> 2, pg = gid & 3;
    float4 o;
    o.x = __ldg(in + (pg * 4 + 0) * 65536 + px);
    o.y = __ldg(in + (pg * 4 + 1) * 65536 + px);
    o.z = __ldg(in + (pg * 4 + 2) * 65536 + px);
    o.w = __ldg(in + (pg * 4 + 3) * 65536 + px);
    g_t4[px * 4 + pg] = o;
}

// One thread = one (pixel, 8-t batch). EXACT R4/R7 arithmetic — do not touch.
__global__ void __launch_bounds__(256) index_k(const float* __restrict__ Fm) {
    const int tid = threadIdx.x;
    const int bt  = tid & 31;
    const int w   = (blockIdx.y << 3) + (tid >> 5);
    const int h   = blockIdx.x;
    const float u = (float)w, v = (float)h;

    const float F0 = __ldg(Fm+0), F1 = __ldg(Fm+1), F2 = __ldg(Fm+2);
    const float F3 = __ldg(Fm+3), F4 = __ldg(Fm+4), F5 = __ldg(Fm+5);
    const float F6 = __ldg(Fm+6), F7 = __ldg(Fm+7), F8 = __ldg(Fm+8);
    float A = __fadd_rn(__fmaf_rn(F3, v, __fmul_rn(F0, u)), F6);
    float B = __fadd_rn(__fmaf_rn(F4, v, __fmul_rn(F1, u)), F7);
    float C = __fadd_rn(__fmaf_rn(F5, v, __fmul_rn(F2, u)), F8);

    const bool col = (fabsf(B) >= fabsf(A));
    float P, Q;
    if (col) { P = A; Q = (fabsf(B) < 1e-8f) ? 1e-8f : B; }
    else     { P = B; Q = (fabsf(A) < 1e-8f) ? 1e-8f : A; }
    const float rq  = __frcp_rn(Q);
    const float nrq = -rq;

    int16_t res[8];
    float tf = (float)(bt * 8);
#pragma unroll
    for (int j = 0; j < 8; ++j, tf += 1.0f) {
        float n  = __fmaf_rn(P, tf, C);
        float yf = __fmul_rn(n, nrq);
        int   ci = __float2int_rn(yf);
        float d  = yf - (float)ci;
        if (0.5f - fabsf(d) < 5e-4f) {
            ci = __float2int_rn(__fdiv_rn(-n, Q));
        }
        res[j] = ((unsigned)ci < 256u) ? (int16_t)ci : (int16_t)(-1);
    }
    reinterpret_cast<uint4*>(g_idx)[(h * 256 + w) * 32 + bt] =
        *reinterpret_cast<const uint4*>(res);
}

// Warp per pixel: RLE the 256-entry index sequence into valid runs.
__global__ void __launch_bounds__(256) rle_k() {
    const int lane = threadIdx.x & 31;
    const int px   = blockIdx.x * 8 + (threadIdx.x >> 5);

    uint4 iv = __ldg(reinterpret_cast<const uint4*>(g_idx) + px * 32 + lane);
    unsigned vals[8];
    vals[0] = iv.x & 0xFFFFu; vals[1] = iv.x >> 16;
    vals[2] = iv.y & 0xFFFFu; vals[3] = iv.y >> 16;
    vals[4] = iv.z & 0xFFFFu; vals[5] = iv.z >> 16;
    vals[6] = iv.w & 0xFFFFu; vals[7] = iv.w >> 16;

    unsigned prev = __shfl_up_sync(FULLM, vals[7], 1);
    if (lane == 0) prev = 0x10000u;                 // t=0 is always a run start

    unsigned m = 0, vm = 0;                         // boundary / valid masks (8 bits)
#pragma unroll
    for (int k = 0; k < 8; ++k) {
        if (vals[k] != prev)      m  |= 1u << k;
        if (vals[k] != 0xFFFFu)   vm |= 1u << k;
        prev = vals[k];
    }

    unsigned cnt = __popc(m & vm);                  // emitted (valid) runs this lane
    unsigned off = cnt;                             // inclusive scan -> exclusive
#pragma unroll
    for (int d = 1; d < 32; d <<= 1) {
        unsigned o = __shfl_up_sync(FULLM, off, d);
        if (lane >= d) off += o;
    }
    unsigned total = __shfl_sync(FULLM, off, 31);
    off -= cnt;
    if (lane == 31) g_nrun[px] = (int)total;

    // cross-lane t1 for this lane's last boundary-started run
    unsigned B = __ballot_sync(FULLM, m != 0);
    unsigned hmask = (lane == 31) ? 0u : (FULLM << (lane + 1));
    unsigned nb = B & hmask;
    int nl = nb ? (__ffs(nb) - 1) : lane;
    unsigned m2 = __shfl_sync(FULLM, m, nl);
    int cross_t1 = nb ? (nl * 8 + __ffs(m2) - 1) : 256;

    unsigned base = (unsigned)px * 264u + off;
#pragma unroll
    for (int k = 0; k < 8; ++k) {
        if (((m >> k) & 1u) && ((vm >> k) & 1u)) {
            unsigned rem = m >> (k + 1);
            int t1 = rem ? (lane * 8 + k + 1 + __ffs(rem) - 1) : cross_t1;
            int t0 = lane * 8 + k;
            g_run[base++] = vals[k] | ((unsigned)t0 << 9) | ((unsigned)t1 << 18);
        }
    }
}

// Warp per (line, pg): exclusive prefix along t. col: line=h, t=w.
__global__ void __launch_bounds__(256) prefix_col_k() {
    const int lane = threadIdx.x & 31;
    const int wg   = blockIdx.x * 8 + (threadIdx.x >> 5);   // 1024 warps
    const int h = wg >> 2, pg = wg & 3;
    float4 carry = make_float4(0.f, 0.f, 0.f, 0.f);
    if (lane == 0) g_pc[(h * 257) * 4 + pg] = carry;
#pragma unroll
    for (int r = 0; r < 8; ++r) {
        int w = r * 32 + lane;
        float4 s = __ldg(g_t4 + (h * 256 + w) * 4 + pg);
#pragma unroll
        for (int d = 1; d < 32; d <<= 1) {
            float ax = __shfl_up_sync(FULLM, s.x, d);
            float ay = __shfl_up_sync(FULLM, s.y, d);
            float az = __shfl_up_sync(FULLM, s.z, d);
            float aw = __shfl_up_sync(FULLM, s.w, d);
            if (lane >= d) { s.x += ax; s.y += ay; s.z += az; s.w += aw; }
        }
        float4 o = make_float4(carry.x + s.x, carry.y + s.y,
                               carry.z + s.z, carry.w + s.w);
        g_pc[(h * 257 + w + 1) * 4 + pg] = o;
        carry.x += __shfl_sync(FULLM, s.x, 31);
        carry.y += __shfl_sync(FULLM, s.y, 31);
        carry.z += __shfl_sync(FULLM, s.z, 31);
        carry.w += __shfl_sync(FULLM, s.w, 31);
    }
}

// row: line=w, t=h.
__global__ void __launch_bounds__(256) prefix_row_k() {
    const int lane = threadIdx.x & 31;
    const int wg   = blockIdx.x * 8 + (threadIdx.x >> 5);
    const int w = wg >> 2, pg = wg & 3;
    float4 carry = make_float4(0.f, 0.f, 0.f, 0.f);
    if (lane == 0) g_pr[(w * 257) * 4 + pg] = carry;
#pragma unroll
    for (int r = 0; r < 8; ++r) {
        int h = r * 32 + lane;
        float4 s = __ldg(g_t4 + (h * 256 + w) * 4 + pg);
#pragma unroll
        for (int d = 1; d < 32; d <<= 1) {
            float ax = __shfl_up_sync(FULLM, s.x, d);
            float ay = __shfl_up_sync(FULLM, s.y, d);
            float az = __shfl_up_sync(FULLM, s.z, d);
            float aw = __shfl_up_sync(FULLM, s.w, d);
            if (lane >= d) { s.x += ax; s.y += ay; s.z += az; s.w += aw; }
        }
        float4 o = make_float4(carry.x + s.x, carry.y + s.y,
                               carry.z + s.z, carry.w + s.w);
        g_pr[(w * 257 + h + 1) * 4 + pg] = o;
        carry.x += __shfl_sync(FULLM, s.x, 31);
        carry.y += __shfl_sync(FULLM, s.y, 31);
        carry.z += __shfl_sync(FULLM, s.z, 31);
        carry.w += __shfl_sync(FULLM, s.w, 31);
    }
}

// Warp = 8 pixels x 4 channel-groups. Per run: 2 endpoint loads, prefix diff.
__global__ void __launch_bounds__(256) gather_k(const float* __restrict__ Fm,
                                                float* __restrict__ out) {
    const int lane = threadIdx.x & 31;
    const int warp = threadIdx.x >> 5;
    const int pg   = lane & 3;
    const int pix  = lane >> 2;
    const int w = blockIdx.y * 64 + warp * 8 + pix;
    const int h = blockIdx.x;
    const int px = h * 256 + w;
    const float u = (float)w, v = (float)h;

    // mode bit — exact same computation as index_k
    const float F0 = __ldg(Fm+0), F1 = __ldg(Fm+1);
    const float F3 = __ldg(Fm+3), F4 = __ldg(Fm+4);
    const float F6 = __ldg(Fm+6), F7 = __ldg(Fm+7);
    float A = __fadd_rn(__fmaf_rn(F3, v, __fmul_rn(F0, u)), F6);
    float B = __fadd_rn(__fmaf_rn(F4, v, __fmul_rn(F1, u)), F7);
    const bool col = (fabsf(B) >= fabsf(A));
    const float4* __restrict__ Ptab = col ? g_pc : g_pr;

    int n = __ldg(g_nrun + px);
    int nmax = n;
#pragma unroll
    for (int d = 16; d; d >>= 1)
        nmax = max(nmax, __shfl_xor_sync(FULLM, nmax, d));

    const uint4* __restrict__ rv =
        reinterpret_cast<const uint4*>(g_run + (size_t)px * 264u);

    float4 acc = make_float4(0.f, 0.f, 0.f, 0.f);
    uint4 V = make_uint4(0u, 0u, 0u, 0u);
    for (int j = 0; j < nmax; ++j) {
        if ((j & 3) == 0) V = __ldg(rv + (j >> 2));
        unsigned word = (j & 3) == 0 ? V.x : (j & 3) == 1 ? V.y
                       : (j & 3) == 2 ? V.z : V.w;
        if (j < n) {
            int ci = word & 511;
            int t0 = (word >> 9) & 511;
            int t1 = word >> 18;
            float4 lo = __ldg(Ptab + (ci * 257 + t0) * 4 + pg);
            float4 hi = __ldg(Ptab + (ci * 257 + t1) * 4 + pg);
            acc.x += hi.x - lo.x;
            acc.y += hi.y - lo.y;
            acc.z += hi.z - lo.z;
            acc.w += hi.w - lo.w;
        }
    }

    out[(pg * 4 + 0) * 65536 + px] = acc.x;
    out[(pg * 4 + 1) * 65536 + px] = acc.y;
    out[(pg * 4 + 2) * 65536 + px] = acc.z;
    out[(pg * 4 + 3) * 65536 + px] = acc.w;
}

extern "C" void kernel_launch(void* const* d_in, const int* in_sizes, int n_in,
                              void* d_out, int out_size) {
    const float* img = (const float*)d_in[0];
    const float* F   = (const float*)d_in[1];
    if (n_in >= 2 && in_sizes[0] == 9) {            // defensive: input order swap
        img = (const float*)d_in[1];
        F   = (const float*)d_in[0];
    }
    float* out = (float*)d_out;

    transpose_k<<<1024, 256>>>(img);
    dim3 gidx(256, 32);
    index_k<<<gidx, 256>>>(F);
    rle_k<<<8192, 256>>>();
    prefix_col_k<<<128, 256>>>();
    prefix_row_k<<<128, 256>>>();
    dim3 ggat(256, 4);
    gather_k<<<ggat, 256>>>(F, out);
}

// round 9
// speedup vs baseline: 1.6254x; 1.1534x over previous
#include <cuda_runtime.h>
#include <cstdint>

// Input:  x (2,8,256,256) fp32, F (3,3) fp32
// Output: (2,8,256,256) fp32 epipolar line-sum.
//
// Pipeline (3 launches):
//  1) transpose_k : x -> g_t4[h][w][pg], 4-plane float4 chunks (64 B/pixel)
//  2) work_k      : blocks 0..255  = col+row exclusive prefix tables
//                   blocks 256..   = warp-per-pixel exact index + in-register RLE
//  3) gather_k    : per run: acc += P[ci][t1] - P[ci][t0]   (2 loads/run)

#define FULLM 0xffffffffu

__device__ float4   g_t4 [256 * 256 * 4];        // 4 MB   repacked image
__device__ unsigned g_run[256 * 256 * 264];      // 69 MB  packed runs: ci|t0<<9|t1<<18
__device__ int      g_nrun[256 * 256];
__device__ float4   g_pc [256 * 257 * 4];        // 4.2MB  col prefix: line=h, t=w
__device__ float4   g_pr [256 * 257 * 4];        // 4.2MB  row prefix: line=w, t=h

__global__ void __launch_bounds__(256) transpose_k(const float* __restrict__ in) {
    int gid = blockIdx.x * 256 + threadIdx.x;    // 262144 = 65536 px * 4 groups
    int px = gid >> 2, pg = gid & 3;
    float4 o;
    o.x = __ldg(in + (pg * 4 + 0) * 65536 + px);
    o.y = __ldg(in + (pg * 4 + 1) * 65536 + px);
    o.z = __ldg(in + (pg * 4 + 2) * 65536 + px);
    o.w = __ldg(in + (pg * 4 + 3) * 65536 + px);
    g_t4[px * 4 + pg] = o;
}

// Warp-serial exclusive prefix of one (line, pg) in direction dir.
__device__ __forceinline__ void prefix_line(int line, int pg, bool is_col, int lane) {
    float4* __restrict__ Pt = is_col ? g_pc : g_pr;
    float4 carry = make_float4(0.f, 0.f, 0.f, 0.f);
    if (lane == 0) Pt[(line * 257) * 4 + pg] = carry;
#pragma unroll
    for (int r = 0; r < 8; ++r) {
        int t = r * 32 + lane;
        int px = is_col ? (line * 256 + t) : (t * 256 + line);
        float4 s = __ldg(g_t4 + px * 4 + pg);
#pragma unroll
        for (int d = 1; d < 32; d <<= 1) {
            float ax = __shfl_up_sync(FULLM, s.x, d);
            float ay = __shfl_up_sync(FULLM, s.y, d);
            float az = __shfl_up_sync(FULLM, s.z, d);
            float aw = __shfl_up_sync(FULLM, s.w, d);
            if (lane >= d) { s.x += ax; s.y += ay; s.z += az; s.w += aw; }
        }
        Pt[(line * 257 + t + 1) * 4 + pg] =
            make_float4(carry.x + s.x, carry.y + s.y, carry.z + s.z, carry.w + s.w);
        carry.x += __shfl_sync(FULLM, s.x, 31);
        carry.y += __shfl_sync(FULLM, s.y, 31);
        carry.z += __shfl_sync(FULLM, s.z, 31);
        carry.w += __shfl_sync(FULLM, s.w, 31);
    }
}

// Warp per pixel: EXACT index arithmetic (R4..R8 — do not touch) + in-register RLE.
__device__ __forceinline__ void idx_rle_pixel(const float* __restrict__ Fm,
                                              int px, int lane) {
    const int w = px & 255, h = px >> 8;
    const float u = (float)w, v = (float)h;

    const float F0 = __ldg(Fm+0), F1 = __ldg(Fm+1), F2 = __ldg(Fm+2);
    const float F3 = __ldg(Fm+3), F4 = __ldg(Fm+4), F5 = __ldg(Fm+5);
    const float F6 = __ldg(Fm+6), F7 = __ldg(Fm+7), F8 = __ldg(Fm+8);
    float A = __fadd_rn(__fmaf_rn(F3, v, __fmul_rn(F0, u)), F6);
    float B = __fadd_rn(__fmaf_rn(F4, v, __fmul_rn(F1, u)), F7);
    float C = __fadd_rn(__fmaf_rn(F5, v, __fmul_rn(F2, u)), F8);

    const bool col = (fabsf(B) >= fabsf(A));
    float P, Q;
    if (col) { P = A; Q = (fabsf(B) < 1e-8f) ? 1e-8f : B; }
    else     { P = B; Q = (fabsf(A) < 1e-8f) ? 1e-8f : A; }
    const float rq  = __frcp_rn(Q);
    const float nrq = -rq;

    unsigned vals[8];
    float tf = (float)(lane * 8);
#pragma unroll
    for (int j = 0; j < 8; ++j, tf += 1.0f) {
        float n  = __fmaf_rn(P, tf, C);
        float yf = __fmul_rn(n, nrq);
        int   ci = __float2int_rn(yf);
        float d  = yf - (float)ci;
        if (0.5f - fabsf(d) < 5e-4f) {
            ci = __float2int_rn(__fdiv_rn(-n, Q));
        }
        vals[j] = ((unsigned)ci < 256u) ? (unsigned)ci : 0xFFFFu;
    }

    unsigned prev = __shfl_up_sync(FULLM, vals[7], 1);
    if (lane == 0) prev = 0x10000u;                 // t=0 always a run start

    unsigned m = 0, vm = 0;
#pragma unroll
    for (int k = 0; k < 8; ++k) {
        if (vals[k] != prev)      m  |= 1u << k;
        if (vals[k] != 0xFFFFu)   vm |= 1u << k;
        prev = vals[k];
    }

    unsigned cnt = __popc(m & vm);
    unsigned off = cnt;
#pragma unroll
    for (int d = 1; d < 32; d <<= 1) {
        unsigned o = __shfl_up_sync(FULLM, off, d);
        if (lane >= d) off += o;
    }
    unsigned total = __shfl_sync(FULLM, off, 31);
    off -= cnt;
    if (lane == 31) g_nrun[px] = (int)total;

    unsigned Bb = __ballot_sync(FULLM, m != 0);
    unsigned hmask = (lane == 31) ? 0u : (FULLM << (lane + 1));
    unsigned nb = Bb & hmask;
    int nl = nb ? (__ffs(nb) - 1) : lane;
    unsigned m2 = __shfl_sync(FULLM, m, nl);
    int cross_t1 = nb ? (nl * 8 + __ffs(m2) - 1) : 256;

    unsigned base = (unsigned)px * 264u + off;
#pragma unroll
    for (int k = 0; k < 8; ++k) {
        if (((m >> k) & 1u) && ((vm >> k) & 1u)) {
            unsigned rem = m >> (k + 1);
            int t1 = rem ? (lane * 8 + k + 1 + __ffs(rem) - 1) : cross_t1;
            int t0 = lane * 8 + k;
            g_run[base++] = vals[k] | ((unsigned)t0 << 9) | ((unsigned)t1 << 18);
        }
    }
}

// blocks 0..255: 2048 prefix warps (dir x 256 lines x 4 pg)
// blocks 256..8447: warp-per-pixel index+RLE (65536 pixels)
__global__ void __launch_bounds__(256) work_k(const float* __restrict__ Fm) {
    const int lane = threadIdx.x & 31;
    const int warp = threadIdx.x >> 5;
    if (blockIdx.x < 256) {
        int wg = blockIdx.x * 8 + warp;             // 0..2047
        prefix_line((wg >> 2) & 255, wg & 3, wg < 1024, lane);
    } else {
        int px = (blockIdx.x - 256) * 8 + warp;     // 0..65535
        idx_rle_pixel(Fm, px, lane);
    }
}

// Warp = 8 pixels x 4 channel-groups. Per run: 2 endpoint loads, prefix diff.
__global__ void __launch_bounds__(256) gather_k(const float* __restrict__ Fm,
                                                float* __restrict__ out) {
    const int lane = threadIdx.x & 31;
    const int warp = threadIdx.x >> 5;
    const int pg   = lane & 3;
    const int pix  = lane >> 2;
    const int w = blockIdx.y * 64 + warp * 8 + pix;
    const int h = blockIdx.x;
    const int px = h * 256 + w;
    const float u = (float)w, v = (float)h;

    // mode bit — exact same computation as idx_rle_pixel
    const float F0 = __ldg(Fm+0), F1 = __ldg(Fm+1);
    const float F3 = __ldg(Fm+3), F4 = __ldg(Fm+4);
    const float F6 = __ldg(Fm+6), F7 = __ldg(Fm+7);
    float A = __fadd_rn(__fmaf_rn(F3, v, __fmul_rn(F0, u)), F6);
    float B = __fadd_rn(__fmaf_rn(F4, v, __fmul_rn(F1, u)), F7);
    const bool col = (fabsf(B) >= fabsf(A));
    const float4* __restrict__ Ptab = col ? g_pc : g_pr;

    int n = __ldg(g_nrun + px);
    int nmax = n;
#pragma unroll
    for (int d = 16; d; d >>= 1)
        nmax = max(nmax, __shfl_xor_sync(FULLM, nmax, d));

    const uint4* __restrict__ rv =
        reinterpret_cast<const uint4*>(g_run + (size_t)px * 264u);

    float4 acc = make_float4(0.f, 0.f, 0.f, 0.f);
    uint4 V = make_uint4(0u, 0u, 0u, 0u);
    for (int j = 0; j < nmax; ++j) {
        if ((j & 3) == 0) V = __ldg(rv + (j >> 2));
        unsigned word = (j & 3) == 0 ? V.x : (j & 3) == 1 ? V.y
                       : (j & 3) == 2 ? V.z : V.w;
        if (j < n) {
            int ci = word & 511;
            int t0 = (word >> 9) & 511;
            int t1 = word >> 18;
            float4 lo = __ldg(Ptab + (ci * 257 + t0) * 4 + pg);
            float4 hi = __ldg(Ptab + (ci * 257 + t1) * 4 + pg);
            acc.x += hi.x - lo.x;
            acc.y += hi.y - lo.y;
            acc.z += hi.z - lo.z;
            acc.w += hi.w - lo.w;
        }
    }

    out[(pg * 4 + 0) * 65536 + px] = acc.x;
    out[(pg * 4 + 1) * 65536 + px] = acc.y;
    out[(pg * 4 + 2) * 65536 + px] = acc.z;
    out[(pg * 4 + 3) * 65536 + px] = acc.w;
}

extern "C" void kernel_launch(void* const* d_in, const int* in_sizes, int n_in,
                              void* d_out, int out_size) {
    const float* img = (const float*)d_in[0];
    const float* F   = (const float*)d_in[1];
    if (n_in >= 2 && in_sizes[0] == 9) {            // defensive: input order swap
        img = (const float*)d_in[1];
        F   = (const float*)d_in[0];
    }
    float* out = (float*)d_out;

    transpose_k<<<1024, 256>>>(img);
    work_k<<<8448, 256>>>(F);
    dim3 ggat(256, 4);
    gather_k<<<ggat, 256>>>(F, out);
}